// round 15
// baseline (speedup 1.0000x reference)
#include <cuda_runtime.h>
#include <cuda_fp16.h>
#include <math.h>
#include <stdint.h>

// ---------------------------------------------------------------------------
#define THREADS   256
#define MPB       64
#define GRID      296            // 2 x 148 SMs, persistent
// k-permutation within each 16-group: pairs (2t,2t+1,2t+8,2t+9) contiguous
__host__ __device__ __forceinline__ int perm16(int k) {
    return ((k >> 1) & 3) * 4 + (k & 1) + ((k >> 3) & 1) * 2;
}

// X smem (single fp16 plane): [ktg 16][m 64][32B]; chunk stride 8192, kt stride 2048
#define OFF_X     0u
#define OFF_BIAS  32768u         // 2056 floats -> 8224B
#define OFF_PART  40992u         // 64*8 floats
#define OFF_OCC   43040u         // 64*8 floats
#define SMEM_TOTAL 45088u

#define SB_B0   0
#define SB_B1   256
#define SB_B2   512
#define SB_WOCC 768
#define SB_WC   1024
#define SB_BC   2048
#define SB_BOCC 2052

// ---------------------------------------------------------------------------
// prepped fp16 weight images: per 64-k chunk [kt 4][n 256][16 halves perm16]
__device__ __align__(16) __half g_W0[16384];
__device__ __align__(16) __half g_W1[4][16384];
__device__ __align__(16) __half g_W2[4][16384];
__device__ __align__(16) float  g_params[2056];

// ---------------------------------------------------------------------------
__device__ __forceinline__ uint32_t smem_u32(const void* p) {
    uint32_t a;
    asm("{ .reg .u64 t; cvta.to.shared.u64 t, %1; cvt.u32.u64 %0, t; }" : "=r"(a) : "l"(p));
    return a;
}
__device__ __forceinline__ void lds64(uint32_t addr, uint32_t& x, uint32_t& y) {
    asm volatile("ld.shared.v2.b32 {%0,%1}, [%2];" : "=r"(x), "=r"(y) : "r"(addr));
}
__device__ __forceinline__ void mma16816(float* c, uint32_t a0, uint32_t a1,
                                         uint32_t a2, uint32_t a3,
                                         uint32_t b0, uint32_t b1) {
    asm volatile(
        "mma.sync.aligned.m16n8k16.row.col.f32.f16.f16.f32 "
        "{%0,%1,%2,%3}, {%4,%5,%6,%7}, {%8,%9}, {%0,%1,%2,%3};"
        : "+f"(c[0]), "+f"(c[1]), "+f"(c[2]), "+f"(c[3])
        : "r"(a0), "r"(a1), "r"(a2), "r"(a3), "r"(b0), "r"(b1));
}
__device__ __forceinline__ uint32_t pack2(float v0, float v1) {
    __half2 h = __floats2half2_rn(v0, v1);
    return *reinterpret_cast<uint32_t*>(&h);
}

// ---------------------------------------------------------------------------
__global__ void prep_kernel(const float* __restrict__ W0,
                            const float* __restrict__ W1,
                            const float* __restrict__ W2,
                            const float* __restrict__ b0,
                            const float* __restrict__ b1,
                            const float* __restrict__ b2,
                            const float* __restrict__ Wocc,
                            const float* __restrict__ bocc,
                            const float* __restrict__ Wc,
                            const float* __restrict__ bc)
{
    int i = blockIdx.x * 256 + threadIdx.x;          // 147456 weights + 2053 params
    if (i >= 147456) {
        int j = i - 147456;
        if (j < 2053) {
            float v;
            if      (j < 256)  v = b0[j];
            else if (j < 512)  v = b1[j - 256];
            else if (j < 768)  v = b2[j - 512];
            else if (j < 1024) v = Wocc[j - 768];
            else if (j < 2048) v = Wc[j - 1024];
            else if (j < 2052) v = bc[j - 2048];
            else               v = bocc[0];
            g_params[j] = v;
        }
        return;
    }
    float v; __half* d; int n, kl;
    if (i < 16384) {
        n = i >> 6; kl = i & 63;
        v = (kl < 63) ? W0[kl * 256 + n] : 0.f;
        d = g_W0;
    } else if (i < 16384 + 65536) {
        int t2 = i - 16384;
        int c = t2 >> 14; n = (t2 >> 6) & 255; kl = t2 & 63;
        v = W1[(c * 64 + kl) * 256 + n];
        d = g_W1[c];
    } else {
        int t2 = i - 16384 - 65536;
        int c = t2 >> 14; n = (t2 >> 6) & 255; kl = t2 & 63;
        v = W2[(c * 64 + kl) * 256 + n];
        d = g_W2[c];
    }
    int kt = kl >> 4, pp = perm16(kl & 15);
    d[kt * 4096 + n * 16 + pp] = __float2half_rn(v);
}

// ---------------------------------------------------------------------------
// one 64-k chunk: A from smem (64m, single fp16 plane), W via direct LDG (32n)
__device__ __forceinline__ void mma_chunk(float acc[4][4][4],
                                          uint32_t a_base,
                                          const __half* __restrict__ wimg,
                                          int ns, int g, int tg)
{
    const char* wp = (const char*)wimg + (uint32_t)(32 * ns + g) * 32 + 8 * tg;
    uint2 wc[4], wn[4];
    #pragma unroll
    for (int nt = 0; nt < 4; nt++) wc[nt] = *(const uint2*)(wp + nt * 256);
    #pragma unroll
    for (int kt = 0; kt < 4; kt++) {
        if (kt < 3) {
            #pragma unroll
            for (int nt = 0; nt < 4; nt++)
                wn[nt] = *(const uint2*)(wp + (kt + 1) * 8192 + nt * 256);
        }
        #pragma unroll
        for (int mt = 0; mt < 4; mt++) {
            uint32_t ab = a_base + kt * 2048 + mt * 512;
            uint32_t a0, a2, a1, a3;
            lds64(ab,       a0, a2);
            lds64(ab + 256, a1, a3);
            #pragma unroll
            for (int nt = 0; nt < 4; nt++)
                mma16816(acc[mt][nt], a0, a1, a2, a3, wc[nt].x, wc[nt].y);
        }
        #pragma unroll
        for (int nt = 0; nt < 4; nt++) wc[nt] = wn[nt];
    }
}

// ---------------------------------------------------------------------------
__global__ __launch_bounds__(THREADS, 2)
void mlp3d_mma(const float* __restrict__ coords,
               float* __restrict__ out, int npts, int ntiles)
{
    extern __shared__ char sm[];
    char*  sx = sm + OFF_X;
    float* s_bias = (float*)(sm + OFF_BIAS);
    float* s_part = (float*)(sm + OFF_PART);   // [m 64][ns 8]
    float* s_occ  = (float*)(sm + OFF_OCC);    // [m 64][ns 8]
    const uint32_t smb = smem_u32(sm);

    const int t = threadIdx.x;
    const int ns = t >> 5, lane = t & 31;      // warp = n-strip (32 cols)
    const int p = ns >> 1;                     // part owned by this warp pair
    const int g = lane >> 2, tg = lane & 3;

    const uint32_t a_rt = smb + OFF_X + (uint32_t)g * 32 + 8 * tg;

    // ---- params -> smem, once per CTA ----
    #pragma unroll
    for (int r = 0; r < 9; r++) {
        int i = t + 256 * r;
        if (i < 2053) s_bias[i] = g_params[i];
    }

    for (int tile = blockIdx.x; tile < ntiles; tile += GRID) {
        const int gbase = tile * MPB;
        __syncthreads();   // prior tile's s_part/s_occ reads + X reads done

        // ---- embedding -> X chunk 0 (64 pts x 64 k), single fp16 plane ----
        if (t < 192) {
            int pt = t & 63, d = t >> 6;
            int eg = gbase + pt;
            float v = (eg < npts) ? coords[eg * 3 + d] : 0.f;
            uint32_t off = (uint32_t)(d >> 4) * 2048u + pt * 32u + perm16(d & 15) * 2u;
            *(__half*)(sx + off) = __float2half_rn(v);
            float f = 1.f;
            #pragma unroll
            for (int fr = 0; fr < 10; fr++) {
                float sv, cv;
                __sincosf(v * f, &sv, &cv);
                int ks = 3 + fr * 6 + d, kc = ks + 3;
                uint32_t os = (uint32_t)(ks >> 4) * 2048u + pt * 32u + perm16(ks & 15) * 2u;
                uint32_t oc = (uint32_t)(kc >> 4) * 2048u + pt * 32u + perm16(kc & 15) * 2u;
                *(__half*)(sx + os) = __float2half_rn(sv);
                *(__half*)(sx + oc) = __float2half_rn(cv);
                f *= 2.f;
            }
        }
        if (t < 64) {   // pad k=63: ktg=3, pp=15
            uint32_t off = 3u * 2048u + t * 32u + 15 * 2u;
            *(uint16_t*)(sx + off) = 0;
        }
        __syncthreads();

        float acc[4][4][4];

        // ================= layer 0 : x = emb @ W0 + b0 ======================
        #pragma unroll
        for (int mt = 0; mt < 4; mt++)
            #pragma unroll
            for (int nt = 0; nt < 4; nt++)
                #pragma unroll
                for (int u = 0; u < 4; u++) acc[mt][nt][u] = 0.f;
        mma_chunk(acc, a_rt, g_W0, ns, g, tg);
        __syncthreads();           // emb reads done

        // epi L0 -> X
        #pragma unroll
        for (int mt = 0; mt < 4; mt++) {
            int r0 = 16 * mt + g;
            #pragma unroll
            for (int nt = 0; nt < 4; nt++) {
                int j0 = 32 * ns + 8 * nt + 2 * tg;
                uint32_t off = (uint32_t)(j0 >> 4) * 2048u + perm16(j0 & 15) * 2u;
                float bb0 = s_bias[SB_B0 + j0], bb1 = s_bias[SB_B0 + j0 + 1];
                *(uint32_t*)(sx + off + r0 * 32) =
                    pack2(acc[mt][nt][0] + bb0, acc[mt][nt][1] + bb1);
                *(uint32_t*)(sx + off + (r0 + 8) * 32) =
                    pack2(acc[mt][nt][2] + bb0, acc[mt][nt][3] + bb1);
            }
        }
        __syncthreads();

        // ================= layer 1 (chunks staggered; part head after 1st) ==
        #pragma unroll
        for (int mt = 0; mt < 4; mt++)
            #pragma unroll
            for (int nt = 0; nt < 4; nt++)
                #pragma unroll
                for (int u = 0; u < 4; u++) acc[mt][nt][u] = 0.f;

        #pragma unroll
        for (int i = 0; i < 4; i++) {
            int c = (p + i) & 3;
            mma_chunk(acc, a_rt + c * 8192, g_W1[c], ns, g, tg);
            if (i == 0) {
                // acc == part-p pre-activation (chunk p only) for this warp's cols
                float pr[4][2];
                #pragma unroll
                for (int mt = 0; mt < 4; mt++) { pr[mt][0] = 0.f; pr[mt][1] = 0.f; }
                #pragma unroll
                for (int mt = 0; mt < 4; mt++)
                    #pragma unroll
                    for (int nt = 0; nt < 4; nt++) {
                        int j0 = 32 * ns + 8 * nt + 2 * tg;
                        float bb0 = s_bias[SB_B1 + j0], bb1 = s_bias[SB_B1 + j0 + 1];
                        float wc0 = s_bias[SB_WC + p * 256 + j0];
                        float wc1 = s_bias[SB_WC + p * 256 + j0 + 1];
                        pr[mt][0] = fmaf(fmaxf(acc[mt][nt][0] + bb0, 0.f), wc0, pr[mt][0]);
                        pr[mt][0] = fmaf(fmaxf(acc[mt][nt][1] + bb1, 0.f), wc1, pr[mt][0]);
                        pr[mt][1] = fmaf(fmaxf(acc[mt][nt][2] + bb0, 0.f), wc0, pr[mt][1]);
                        pr[mt][1] = fmaf(fmaxf(acc[mt][nt][3] + bb1, 0.f), wc1, pr[mt][1]);
                    }
                #pragma unroll
                for (int mt = 0; mt < 4; mt++)
                    #pragma unroll
                    for (int hh = 0; hh < 2; hh++) {
                        float v = pr[mt][hh];
                        v += __shfl_xor_sync(0xffffffffu, v, 1);
                        v += __shfl_xor_sync(0xffffffffu, v, 2);
                        if (tg == 0)
                            s_part[(16 * mt + g + 8 * hh) * 8 + ns] = v;
                    }
            }
        }
        __syncthreads();           // all X reads done

        // epi L1: y = relu(acc + b1) -> X
        #pragma unroll
        for (int mt = 0; mt < 4; mt++) {
            int r0 = 16 * mt + g;
            #pragma unroll
            for (int nt = 0; nt < 4; nt++) {
                int j0 = 32 * ns + 8 * nt + 2 * tg;
                uint32_t off = (uint32_t)(j0 >> 4) * 2048u + perm16(j0 & 15) * 2u;
                float bb0 = s_bias[SB_B1 + j0], bb1 = s_bias[SB_B1 + j0 + 1];
                *(uint32_t*)(sx + off + r0 * 32) =
                    pack2(fmaxf(acc[mt][nt][0] + bb0, 0.f),
                          fmaxf(acc[mt][nt][1] + bb1, 0.f));
                *(uint32_t*)(sx + off + (r0 + 8) * 32) =
                    pack2(fmaxf(acc[mt][nt][2] + bb0, 0.f),
                          fmaxf(acc[mt][nt][3] + bb1, 0.f));
            }
        }
        __syncthreads();

        // ================= layer 2 =========================================
        #pragma unroll
        for (int mt = 0; mt < 4; mt++)
            #pragma unroll
            for (int nt = 0; nt < 4; nt++)
                #pragma unroll
                for (int u = 0; u < 4; u++) acc[mt][nt][u] = 0.f;

        #pragma unroll
        for (int i = 0; i < 4; i++) {
            int c = (p + i) & 3;
            mma_chunk(acc, a_rt + c * 8192, g_W2[c], ns, g, tg);
        }

        // ---- occ head ----
        {
            float pr[4][2];
            #pragma unroll
            for (int mt = 0; mt < 4; mt++) { pr[mt][0] = 0.f; pr[mt][1] = 0.f; }
            #pragma unroll
            for (int mt = 0; mt < 4; mt++)
                #pragma unroll
                for (int nt = 0; nt < 4; nt++) {
                    int j0 = 32 * ns + 8 * nt + 2 * tg;
                    float bb0 = s_bias[SB_B2 + j0], bb1 = s_bias[SB_B2 + j0 + 1];
                    float wo0 = s_bias[SB_WOCC + j0], wo1 = s_bias[SB_WOCC + j0 + 1];
                    pr[mt][0] = fmaf(fmaxf(acc[mt][nt][0] + bb0, 0.f), wo0, pr[mt][0]);
                    pr[mt][0] = fmaf(fmaxf(acc[mt][nt][1] + bb1, 0.f), wo1, pr[mt][0]);
                    pr[mt][1] = fmaf(fmaxf(acc[mt][nt][2] + bb0, 0.f), wo0, pr[mt][1]);
                    pr[mt][1] = fmaf(fmaxf(acc[mt][nt][3] + bb1, 0.f), wo1, pr[mt][1]);
                }
            #pragma unroll
            for (int mt = 0; mt < 4; mt++)
                #pragma unroll
                for (int hh = 0; hh < 2; hh++) {
                    float v = pr[mt][hh];
                    v += __shfl_xor_sync(0xffffffffu, v, 1);
                    v += __shfl_xor_sync(0xffffffffu, v, 2);
                    if (tg == 0)
                        s_occ[(16 * mt + g + 8 * hh) * 8 + ns] = v;
                }
        }
        __syncthreads();

        // ---- final stores ----
        if (t < 64) {
            int gm = gbase + t;
            if (gm < npts) {
                float s = s_bias[SB_BOCC];
                #pragma unroll
                for (int w = 0; w < 8; w++) s += s_occ[t * 8 + w];
                out[gm] = s;
            }
        }
        {
            int m = t >> 2, pp = t & 3;
            int gm = gbase + m;
            if (gm < npts)
                out[npts + gm * 4 + pp] =
                    s_part[m * 8 + 2 * pp] + s_part[m * 8 + 2 * pp + 1] +
                    s_bias[SB_BC + pp];
        }
    }
}

// ---------------------------------------------------------------------------
extern "C" void kernel_launch(void* const* d_in, const int* in_sizes, int n_in,
                              void* d_out, int out_size)
{
    const float* coords = (const float*)d_in[0];
    const float* W0   = (const float*)d_in[1];
    const float* b0   = (const float*)d_in[2];
    const float* W1   = (const float*)d_in[3];
    const float* b1   = (const float*)d_in[4];
    const float* W2   = (const float*)d_in[5];
    const float* b2   = (const float*)d_in[6];
    const float* Wocc = (const float*)d_in[7];
    const float* bocc = (const float*)d_in[8];
    const float* Wc   = (const float*)d_in[9];
    const float* bc   = (const float*)d_in[10];
    float* out = (float*)d_out;

    int npts = in_sizes[0] / 3;
    int ntiles = (npts + MPB - 1) / MPB;

    prep_kernel<<<585, 256>>>(W0, W1, W2, b0, b1, b2, Wocc, bocc, Wc, bc);

    cudaFuncSetAttribute(mlp3d_mma, cudaFuncAttributeMaxDynamicSharedMemorySize,
                         (int)SMEM_TOTAL);
    mlp3d_mma<<<GRID, THREADS, SMEM_TOTAL>>>(coords, out, npts, ntiles);
    (void)n_in; (void)out_size;
}

// round 16
// speedup vs baseline: 1.0078x; 1.0078x over previous
#include <cuda_runtime.h>
#include <cuda_fp16.h>
#include <math.h>
#include <stdint.h>

// ---------------------------------------------------------------------------
#define THREADS   256
#define MPB       32             // points per block (tile 32m x 256n)
// k-permutation within each 16-group: pairs (2t,2t+1,2t+8,2t+9) contiguous
__host__ __device__ __forceinline__ int perm16(int k) {
    return ((k >> 1) & 3) * 4 + (k & 1) + ((k >> 3) & 1) * 2;
}

// X smem (single fp16 plane): [ktg 16][m 32][32B]; chunk stride 4096, ktg stride 1024
#define OFF_X     0u             // 16384B
#define OFF_BIAS  16384u         // 2053 floats -> 8224B
#define OFF_PART  24608u         // 32*8 floats = 1024B
#define OFF_OCC   25632u         // 32*8 floats = 1024B
#define SMEM_TOTAL 26656u

#define SB_B0   0
#define SB_B1   256
#define SB_B2   512
#define SB_WOCC 768
#define SB_WC   1024
#define SB_BC   2048
#define SB_BOCC 2052

// ---------------------------------------------------------------------------
// prepped fp16 weight images: per 64-k chunk [kt 4][n 256][16 halves perm16]
__device__ __align__(16) __half g_W0[16384];
__device__ __align__(16) __half g_W1[4][16384];
__device__ __align__(16) __half g_W2[4][16384];
__device__ __align__(16) float  g_params[2056];

// ---------------------------------------------------------------------------
__device__ __forceinline__ uint32_t smem_u32(const void* p) {
    uint32_t a;
    asm("{ .reg .u64 t; cvta.to.shared.u64 t, %1; cvt.u32.u64 %0, t; }" : "=r"(a) : "l"(p));
    return a;
}
__device__ __forceinline__ void lds64(uint32_t addr, uint32_t& x, uint32_t& y) {
    asm volatile("ld.shared.v2.b32 {%0,%1}, [%2];" : "=r"(x), "=r"(y) : "r"(addr));
}
__device__ __forceinline__ void mma16816(float* c, uint32_t a0, uint32_t a1,
                                         uint32_t a2, uint32_t a3,
                                         uint32_t b0, uint32_t b1) {
    asm volatile(
        "mma.sync.aligned.m16n8k16.row.col.f32.f16.f16.f32 "
        "{%0,%1,%2,%3}, {%4,%5,%6,%7}, {%8,%9}, {%0,%1,%2,%3};"
        : "+f"(c[0]), "+f"(c[1]), "+f"(c[2]), "+f"(c[3])
        : "r"(a0), "r"(a1), "r"(a2), "r"(a3), "r"(b0), "r"(b1));
}
__device__ __forceinline__ uint32_t pack2(float v0, float v1) {
    __half2 h = __floats2half2_rn(v0, v1);
    return *reinterpret_cast<uint32_t*>(&h);
}

// ---------------------------------------------------------------------------
__global__ void prep_kernel(const float* __restrict__ W0,
                            const float* __restrict__ W1,
                            const float* __restrict__ W2,
                            const float* __restrict__ b0,
                            const float* __restrict__ b1,
                            const float* __restrict__ b2,
                            const float* __restrict__ Wocc,
                            const float* __restrict__ bocc,
                            const float* __restrict__ Wc,
                            const float* __restrict__ bc)
{
    int i = blockIdx.x * 256 + threadIdx.x;          // 147456 weights + 2053 params
    if (i >= 147456) {
        int j = i - 147456;
        if (j < 2053) {
            float v;
            if      (j < 256)  v = b0[j];
            else if (j < 512)  v = b1[j - 256];
            else if (j < 768)  v = b2[j - 512];
            else if (j < 1024) v = Wocc[j - 768];
            else if (j < 2048) v = Wc[j - 1024];
            else if (j < 2052) v = bc[j - 2048];
            else               v = bocc[0];
            g_params[j] = v;
        }
        return;
    }
    float v; __half* d; int n, kl;
    if (i < 16384) {
        n = i >> 6; kl = i & 63;
        v = (kl < 63) ? W0[kl * 256 + n] : 0.f;
        d = g_W0;
    } else if (i < 16384 + 65536) {
        int t2 = i - 16384;
        int c = t2 >> 14; n = (t2 >> 6) & 255; kl = t2 & 63;
        v = W1[(c * 64 + kl) * 256 + n];
        d = g_W1[c];
    } else {
        int t2 = i - 16384 - 65536;
        int c = t2 >> 14; n = (t2 >> 6) & 255; kl = t2 & 63;
        v = W2[(c * 64 + kl) * 256 + n];
        d = g_W2[c];
    }
    int kt = kl >> 4, pp = perm16(kl & 15);
    d[kt * 4096 + n * 16 + pp] = __float2half_rn(v);
}

// ---------------------------------------------------------------------------
// one 64-k chunk: A from smem (32m, single fp16 plane), W via direct LDG (32n)
__device__ __forceinline__ void mma_chunk(float acc[2][4][4],
                                          uint32_t a_base,
                                          const __half* __restrict__ wimg,
                                          int ns, int g, int tg)
{
    const char* wp = (const char*)wimg + (uint32_t)(32 * ns + g) * 32 + 8 * tg;
    uint2 wc[4], wn[4];
    #pragma unroll
    for (int nt = 0; nt < 4; nt++) wc[nt] = *(const uint2*)(wp + nt * 256);
    #pragma unroll
    for (int kt = 0; kt < 4; kt++) {
        if (kt < 3) {
            #pragma unroll
            for (int nt = 0; nt < 4; nt++)
                wn[nt] = *(const uint2*)(wp + (kt + 1) * 8192 + nt * 256);
        }
        #pragma unroll
        for (int mt = 0; mt < 2; mt++) {
            uint32_t ab = a_base + kt * 1024 + mt * 512;
            uint32_t a0, a2, a1, a3;
            lds64(ab,       a0, a2);
            lds64(ab + 256, a1, a3);
            #pragma unroll
            for (int nt = 0; nt < 4; nt++)
                mma16816(acc[mt][nt], a0, a1, a2, a3, wc[nt].x, wc[nt].y);
        }
        #pragma unroll
        for (int nt = 0; nt < 4; nt++) wc[nt] = wn[nt];
    }
}

// ---------------------------------------------------------------------------
__global__ __launch_bounds__(THREADS, 3)
void mlp3d_mma(const float* __restrict__ coords,
               float* __restrict__ out, int npts)
{
    extern __shared__ char sm[];
    char*  sx = sm + OFF_X;
    float* s_bias = (float*)(sm + OFF_BIAS);
    float* s_part = (float*)(sm + OFF_PART);   // [m 32][ns 8]
    float* s_occ  = (float*)(sm + OFF_OCC);    // [m 32][ns 8]
    const uint32_t smb = smem_u32(sm);

    const int t = threadIdx.x;
    const int ns = t >> 5, lane = t & 31;      // warp = n-strip (32 cols)
    const int p = ns >> 1;                     // part owned by this warp pair
    const int g = lane >> 2, tg = lane & 3;
    const int gbase = blockIdx.x * MPB;

    const uint32_t a_rt = smb + OFF_X + (uint32_t)g * 32 + 8 * tg;

    // ---- params -> smem (branch-free from prepacked image) ----
    #pragma unroll
    for (int r = 0; r < 9; r++) {
        int i = t + 256 * r;
        if (i < 2053) s_bias[i] = g_params[i];
    }

    // ---- embedding -> X chunk 0 (32 pts x 64 k), single fp16 plane ----
    if (t < 96) {
        int pt = t & 31, d = t >> 5;
        int eg = gbase + pt;
        float v = (eg < npts) ? coords[eg * 3 + d] : 0.f;
        uint32_t off = (uint32_t)(d >> 4) * 1024u + pt * 32u + perm16(d & 15) * 2u;
        *(__half*)(sx + off) = __float2half_rn(v);
        float f = 1.f;
        #pragma unroll
        for (int fr = 0; fr < 10; fr++) {
            float sv, cv;
            __sincosf(v * f, &sv, &cv);
            int ks = 3 + fr * 6 + d, kc = ks + 3;
            uint32_t os = (uint32_t)(ks >> 4) * 1024u + pt * 32u + perm16(ks & 15) * 2u;
            uint32_t oc = (uint32_t)(kc >> 4) * 1024u + pt * 32u + perm16(kc & 15) * 2u;
            *(__half*)(sx + os) = __float2half_rn(sv);
            *(__half*)(sx + oc) = __float2half_rn(cv);
            f *= 2.f;
        }
    }
    if (t < 32) {   // pad k=63: ktg=3, pp=15
        uint32_t off = 3u * 1024u + t * 32u + 15 * 2u;
        *(uint16_t*)(sx + off) = 0;
    }
    __syncthreads();

    float acc[2][4][4];

    // ================= layer 0 : x = emb @ W0 + b0 ==========================
    #pragma unroll
    for (int mt = 0; mt < 2; mt++)
        #pragma unroll
        for (int nt = 0; nt < 4; nt++)
            #pragma unroll
            for (int u = 0; u < 4; u++) acc[mt][nt][u] = 0.f;
    mma_chunk(acc, a_rt, g_W0, ns, g, tg);
    __syncthreads();               // emb reads done

    // epi L0 -> X
    #pragma unroll
    for (int mt = 0; mt < 2; mt++) {
        int r0 = 16 * mt + g;
        #pragma unroll
        for (int nt = 0; nt < 4; nt++) {
            int j0 = 32 * ns + 8 * nt + 2 * tg;
            uint32_t off = (uint32_t)(j0 >> 4) * 1024u + perm16(j0 & 15) * 2u;
            float bb0 = s_bias[SB_B0 + j0], bb1 = s_bias[SB_B0 + j0 + 1];
            *(uint32_t*)(sx + off + r0 * 32) =
                pack2(acc[mt][nt][0] + bb0, acc[mt][nt][1] + bb1);
            *(uint32_t*)(sx + off + (r0 + 8) * 32) =
                pack2(acc[mt][nt][2] + bb0, acc[mt][nt][3] + bb1);
        }
    }
    __syncthreads();

    // ================= layer 1 (chunks staggered; part head after 1st) =====
    #pragma unroll
    for (int mt = 0; mt < 2; mt++)
        #pragma unroll
        for (int nt = 0; nt < 4; nt++)
            #pragma unroll
            for (int u = 0; u < 4; u++) acc[mt][nt][u] = 0.f;

    #pragma unroll
    for (int i = 0; i < 4; i++) {
        int c = (p + i) & 3;
        mma_chunk(acc, a_rt + c * 4096, g_W1[c], ns, g, tg);
        if (i == 0) {
            // acc == part-p pre-activation (chunk p only) for this warp's cols
            float pr[2][2];
            #pragma unroll
            for (int mt = 0; mt < 2; mt++) { pr[mt][0] = 0.f; pr[mt][1] = 0.f; }
            #pragma unroll
            for (int mt = 0; mt < 2; mt++)
                #pragma unroll
                for (int nt = 0; nt < 4; nt++) {
                    int j0 = 32 * ns + 8 * nt + 2 * tg;
                    float bb0 = s_bias[SB_B1 + j0], bb1 = s_bias[SB_B1 + j0 + 1];
                    float wc0 = s_bias[SB_WC + p * 256 + j0];
                    float wc1 = s_bias[SB_WC + p * 256 + j0 + 1];
                    pr[mt][0] = fmaf(fmaxf(acc[mt][nt][0] + bb0, 0.f), wc0, pr[mt][0]);
                    pr[mt][0] = fmaf(fmaxf(acc[mt][nt][1] + bb1, 0.f), wc1, pr[mt][0]);
                    pr[mt][1] = fmaf(fmaxf(acc[mt][nt][2] + bb0, 0.f), wc0, pr[mt][1]);
                    pr[mt][1] = fmaf(fmaxf(acc[mt][nt][3] + bb1, 0.f), wc1, pr[mt][1]);
                }
            #pragma unroll
            for (int mt = 0; mt < 2; mt++)
                #pragma unroll
                for (int hh = 0; hh < 2; hh++) {
                    float v = pr[mt][hh];
                    v += __shfl_xor_sync(0xffffffffu, v, 1);
                    v += __shfl_xor_sync(0xffffffffu, v, 2);
                    if (tg == 0)
                        s_part[(16 * mt + g + 8 * hh) * 8 + ns] = v;
                }
        }
    }
    __syncthreads();               // all X reads done

    // epi L1: y = relu(acc + b1) -> X
    #pragma unroll
    for (int mt = 0; mt < 2; mt++) {
        int r0 = 16 * mt + g;
        #pragma unroll
        for (int nt = 0; nt < 4; nt++) {
            int j0 = 32 * ns + 8 * nt + 2 * tg;
            uint32_t off = (uint32_t)(j0 >> 4) * 1024u + perm16(j0 & 15) * 2u;
            float bb0 = s_bias[SB_B1 + j0], bb1 = s_bias[SB_B1 + j0 + 1];
            *(uint32_t*)(sx + off + r0 * 32) =
                pack2(fmaxf(acc[mt][nt][0] + bb0, 0.f),
                      fmaxf(acc[mt][nt][1] + bb1, 0.f));
            *(uint32_t*)(sx + off + (r0 + 8) * 32) =
                pack2(fmaxf(acc[mt][nt][2] + bb0, 0.f),
                      fmaxf(acc[mt][nt][3] + bb1, 0.f));
        }
    }
    __syncthreads();

    // ================= layer 2 =============================================
    #pragma unroll
    for (int mt = 0; mt < 2; mt++)
        #pragma unroll
        for (int nt = 0; nt < 4; nt++)
            #pragma unroll
            for (int u = 0; u < 4; u++) acc[mt][nt][u] = 0.f;

    #pragma unroll
    for (int i = 0; i < 4; i++) {
        int c = (p + i) & 3;
        mma_chunk(acc, a_rt + c * 4096, g_W2[c], ns, g, tg);
    }

    // ---- occ head ----
    {
        float pr[2][2];
        #pragma unroll
        for (int mt = 0; mt < 2; mt++) { pr[mt][0] = 0.f; pr[mt][1] = 0.f; }
        #pragma unroll
        for (int mt = 0; mt < 2; mt++)
            #pragma unroll
            for (int nt = 0; nt < 4; nt++) {
                int j0 = 32 * ns + 8 * nt + 2 * tg;
                float bb0 = s_bias[SB_B2 + j0], bb1 = s_bias[SB_B2 + j0 + 1];
                float wo0 = s_bias[SB_WOCC + j0], wo1 = s_bias[SB_WOCC + j0 + 1];
                pr[mt][0] = fmaf(fmaxf(acc[mt][nt][0] + bb0, 0.f), wo0, pr[mt][0]);
                pr[mt][0] = fmaf(fmaxf(acc[mt][nt][1] + bb1, 0.f), wo1, pr[mt][0]);
                pr[mt][1] = fmaf(fmaxf(acc[mt][nt][2] + bb0, 0.f), wo0, pr[mt][1]);
                pr[mt][1] = fmaf(fmaxf(acc[mt][nt][3] + bb1, 0.f), wo1, pr[mt][1]);
            }
        #pragma unroll
        for (int mt = 0; mt < 2; mt++)
            #pragma unroll
            for (int hh = 0; hh < 2; hh++) {
                float v = pr[mt][hh];
                v += __shfl_xor_sync(0xffffffffu, v, 1);
                v += __shfl_xor_sync(0xffffffffu, v, 2);
                if (tg == 0)
                    s_occ[(16 * mt + g + 8 * hh) * 8 + ns] = v;
            }
    }
    __syncthreads();

    // ---- final stores ----
    if (t < 32) {
        int gm = gbase + t;
        if (gm < npts) {
            float s = s_bias[SB_BOCC];
            #pragma unroll
            for (int w = 0; w < 8; w++) s += s_occ[t * 8 + w];
            out[gm] = s;
        }
    }
    if (t < 128) {
        int m = t >> 2, pp = t & 3;
        int gm = gbase + m;
        if (gm < npts)
            out[npts + gm * 4 + pp] =
                s_part[m * 8 + 2 * pp] + s_part[m * 8 + 2 * pp + 1] +
                s_bias[SB_BC + pp];
    }
}

// ---------------------------------------------------------------------------
extern "C" void kernel_launch(void* const* d_in, const int* in_sizes, int n_in,
                              void* d_out, int out_size)
{
    const float* coords = (const float*)d_in[0];
    const float* W0   = (const float*)d_in[1];
    const float* b0   = (const float*)d_in[2];
    const float* W1   = (const float*)d_in[3];
    const float* b1   = (const float*)d_in[4];
    const float* W2   = (const float*)d_in[5];
    const float* b2   = (const float*)d_in[6];
    const float* Wocc = (const float*)d_in[7];
    const float* bocc = (const float*)d_in[8];
    const float* Wc   = (const float*)d_in[9];
    const float* bc   = (const float*)d_in[10];
    float* out = (float*)d_out;

    int npts = in_sizes[0] / 3;
    int blocks = (npts + MPB - 1) / MPB;

    prep_kernel<<<585, 256>>>(W0, W1, W2, b0, b1, b2, Wocc, bocc, Wc, bc);

    cudaFuncSetAttribute(mlp3d_mma, cudaFuncAttributeMaxDynamicSharedMemorySize,
                         (int)SMEM_TOTAL);
    mlp3d_mma<<<blocks, THREADS, SMEM_TOTAL>>>(coords, out, npts);
    (void)n_in; (void)out_size;
}

// round 17
// speedup vs baseline: 1.0940x; 1.0855x over previous
#include <cuda_runtime.h>
#include <cuda_fp16.h>
#include <math.h>
#include <stdint.h>

// ---------------------------------------------------------------------------
#define THREADS   256
#define MPB       64
// k-permutation within each 16-group: pairs (2t,2t+1,2t+8,2t+9) contiguous
__host__ __device__ __forceinline__ int perm16(int k) {
    return ((k >> 1) & 3) * 4 + (k & 1) + ((k >> 3) & 1) * 2;
}

// X smem, fragment-slot layout (fp16):
//   addr = ktg*2048 + mt*512 + g*64 + slot*16 + word*4 + inner*2
//   slot = (tq + (g>>1)) & 3   (XOR-rotation kills store bank conflicts)
//   16B slot content = [a0|a1|a2|a3] = [row g,klo | row g+8,klo | row g,khi | row g+8,khi]
#define OFF_X     0u             // 32768B
#define OFF_BIAS  32768u         // 2053 floats -> 8224B
#define OFF_PART  40992u         // 64*8 floats
#define OFF_OCC   43040u         // 64*8 floats
#define SMEM_TOTAL 45088u

#define SB_B0   0
#define SB_B1   256
#define SB_B2   512
#define SB_WOCC 768
#define SB_WC   1024
#define SB_BC   2048
#define SB_BOCC 2052

// ---------------------------------------------------------------------------
// prepped fp16 weight images, fragment-packed per 64-k chunk:
//   [kt 4][ns 8][lane 32][nt 4][8B] -> byte = kt*8192 + ns*1024 + lane*32 + nt*8
__device__ __align__(16) __half g_W0[16384];
__device__ __align__(16) __half g_W1[4][16384];
__device__ __align__(16) __half g_W2[4][16384];

// ---------------------------------------------------------------------------
__device__ __forceinline__ uint32_t smem_u32(const void* p) {
    uint32_t a;
    asm("{ .reg .u64 t; cvta.to.shared.u64 t, %1; cvt.u32.u64 %0, t; }" : "=r"(a) : "l"(p));
    return a;
}
__device__ __forceinline__ void lds128(uint32_t addr, uint4& v) {
    asm volatile("ld.shared.v4.b32 {%0,%1,%2,%3}, [%4];"
                 : "=r"(v.x), "=r"(v.y), "=r"(v.z), "=r"(v.w) : "r"(addr));
}
__device__ __forceinline__ void sts64(uint32_t addr, uint32_t v0, uint32_t v1) {
    asm volatile("st.shared.v2.b32 [%0], {%1,%2};" :: "r"(addr), "r"(v0), "r"(v1));
}
__device__ __forceinline__ void mma16816(float* c, uint32_t a0, uint32_t a1,
                                         uint32_t a2, uint32_t a3,
                                         uint32_t b0, uint32_t b1) {
    asm volatile(
        "mma.sync.aligned.m16n8k16.row.col.f32.f16.f16.f32 "
        "{%0,%1,%2,%3}, {%4,%5,%6,%7}, {%8,%9}, {%0,%1,%2,%3};"
        : "+f"(c[0]), "+f"(c[1]), "+f"(c[2]), "+f"(c[3])
        : "r"(a0), "r"(a1), "r"(a2), "r"(a3), "r"(b0), "r"(b1));
}
__device__ __forceinline__ uint32_t pack2(float v0, float v1) {
    __half2 h = __floats2half2_rn(v0, v1);
    return *reinterpret_cast<uint32_t*>(&h);
}
// byte address of element (k, m) in the X image
__device__ __forceinline__ uint32_t xaddr(int k, int m) {
    int pp = perm16(k & 15);
    int g = m & 7;
    return (uint32_t)((k >> 4) * 2048 + (m >> 4) * 512 + g * 64
         + ((((pp >> 2) + (g >> 1)) & 3) * 16)
         + ((((m >> 3) & 1) + ((pp >> 1) & 1) * 2) * 4)
         + ((pp & 1) * 2));
}

// ---------------------------------------------------------------------------
__global__ void prep_kernel(const float* __restrict__ W0,
                            const float* __restrict__ W1,
                            const float* __restrict__ W2)
{
    int i = blockIdx.x * 256 + threadIdx.x;          // 147456 total
    float v; __half* d; int n, kl;
    if (i < 16384) {
        n = i >> 6; kl = i & 63;
        v = (kl < 63) ? W0[kl * 256 + n] : 0.f;
        d = g_W0;
    } else if (i < 16384 + 65536) {
        int t2 = i - 16384;
        int c = t2 >> 14; n = (t2 >> 6) & 255; kl = t2 & 63;
        v = W1[(c * 64 + kl) * 256 + n];
        d = g_W1[c];
    } else {
        int t2 = i - 16384 - 65536;
        if (t2 >= 65536) return;
        int c = t2 >> 14; n = (t2 >> 6) & 255; kl = t2 & 63;
        v = W2[(c * 64 + kl) * 256 + n];
        d = g_W2[c];
    }
    int kt = kl >> 4, pp = perm16(kl & 15);
    int ns_ = n >> 5, nt = (n >> 3) & 3, g = n & 7;
    int tg = pp >> 2, inner = pp & 3;
    d[kt * 4096 + ns_ * 512 + (4 * g + tg) * 16 + nt * 4 + inner] = __float2half_rn(v);
}

// ---------------------------------------------------------------------------
// one 64-k chunk: A via conflict-free LDS.128, W via 8 upfront LDG.128 (32n)
__device__ __forceinline__ void mma_chunk(float acc[4][4][4],
                                          uint32_t a_base,
                                          const __half* __restrict__ wimg,
                                          int ns, int lane)
{
    const char* wp = (const char*)wimg + (uint32_t)ns * 1024u + (uint32_t)lane * 32u;
    uint4 w[4][2];
    #pragma unroll
    for (int kt = 0; kt < 4; kt++) {
        w[kt][0] = *(const uint4*)(wp + kt * 8192);
        w[kt][1] = *(const uint4*)(wp + kt * 8192 + 16);
    }
    #pragma unroll
    for (int kt = 0; kt < 4; kt++) {
        #pragma unroll
        for (int mt = 0; mt < 4; mt++) {
            uint4 a;
            lds128(a_base + kt * 2048 + mt * 512, a);
            mma16816(acc[mt][0], a.x, a.y, a.z, a.w, w[kt][0].x, w[kt][0].y);
            mma16816(acc[mt][1], a.x, a.y, a.z, a.w, w[kt][0].z, w[kt][0].w);
            mma16816(acc[mt][2], a.x, a.y, a.z, a.w, w[kt][1].x, w[kt][1].y);
            mma16816(acc[mt][3], a.x, a.y, a.z, a.w, w[kt][1].z, w[kt][1].w);
        }
    }
}

// ---------------------------------------------------------------------------
__global__ __launch_bounds__(THREADS, 2)
void mlp3d_mma(const float* __restrict__ coords,
               const float* __restrict__ b0, const float* __restrict__ b1,
               const float* __restrict__ b2,
               const float* __restrict__ Wocc, const float* __restrict__ bocc,
               const float* __restrict__ Wc, const float* __restrict__ bc,
               float* __restrict__ out, int npts)
{
    extern __shared__ char sm[];
    char*  sx = sm + OFF_X;
    float* s_bias = (float*)(sm + OFF_BIAS);
    float* s_part = (float*)(sm + OFF_PART);   // [m 64][ns 8]
    float* s_occ  = (float*)(sm + OFF_OCC);    // [m 64][ns 8]
    const uint32_t smb = smem_u32(sm);

    const int t = threadIdx.x;
    const int ns = t >> 5, lane = t & 31;      // warp = n-strip (32 cols)
    const int p = ns >> 1;                     // part owned by this warp pair
    const int g = lane >> 2, tg = lane & 3;
    const int gbase = blockIdx.x * MPB;

    const uint32_t a_rt = smb + OFF_X + (uint32_t)g * 64u
                        + (uint32_t)(((tg + (g >> 1)) & 3) * 16);
    // epilogue store base (same slot math, word offset added per nt)
    const uint32_t e_rt = a_rt;

    // ---- biases / heads -> smem ----
    for (int i = t; i < 2053; i += THREADS) {
        float v;
        if      (i < 256)  v = b0[i];
        else if (i < 512)  v = b1[i - 256];
        else if (i < 768)  v = b2[i - 512];
        else if (i < 1024) v = Wocc[i - 768];
        else if (i < 2048) v = Wc[i - 1024];
        else if (i < 2052) v = bc[i - 2048];
        else               v = bocc[0];
        s_bias[i] = v;
    }

    // ---- embedding -> X chunk 0 (64 pts x 64 k) ----
    if (t < 192) {
        int pt = t & 63, d = t >> 6;
        int eg = gbase + pt;
        float v = (eg < npts) ? coords[eg * 3 + d] : 0.f;
        *(__half*)(sx + xaddr(d, pt)) = __float2half_rn(v);
        float f = 1.f;
        #pragma unroll
        for (int fr = 0; fr < 10; fr++) {
            float sv, cv;
            __sincosf(v * f, &sv, &cv);
            int ks = 3 + fr * 6 + d, kc = ks + 3;
            *(__half*)(sx + xaddr(ks, pt)) = __float2half_rn(sv);
            *(__half*)(sx + xaddr(kc, pt)) = __float2half_rn(cv);
            f *= 2.f;
        }
    }
    if (t < 64) *(uint16_t*)(sx + xaddr(63, t)) = 0;   // pad k=63
    __syncthreads();

    float acc[4][4][4];

    // ================= layer 0 : x = emb @ W0 + b0 ==========================
    #pragma unroll
    for (int mt = 0; mt < 4; mt++)
        #pragma unroll
        for (int nt = 0; nt < 4; nt++)
            #pragma unroll
            for (int u = 0; u < 4; u++) acc[mt][nt][u] = 0.f;
    mma_chunk(acc, a_rt, g_W0, ns, lane);
    __syncthreads();               // emb reads done

    // epi L0 -> X  (one STS.64 per (mt,nt))
    #pragma unroll
    for (int mt = 0; mt < 4; mt++) {
        #pragma unroll
        for (int nt = 0; nt < 4; nt++) {
            int j0 = 32 * ns + 8 * nt + 2 * tg;
            float bb0 = s_bias[SB_B0 + j0], bb1 = s_bias[SB_B0 + j0 + 1];
            uint32_t dst = e_rt + (uint32_t)(j0 >> 4) * 2048u + (uint32_t)mt * 512u
                         + (uint32_t)((nt & 1) * 8);
            sts64(dst, pack2(acc[mt][nt][0] + bb0, acc[mt][nt][1] + bb1),
                       pack2(acc[mt][nt][2] + bb0, acc[mt][nt][3] + bb1));
        }
    }
    __syncthreads();

    // ================= layer 1 (chunks staggered; part head after 1st) =====
    #pragma unroll
    for (int mt = 0; mt < 4; mt++)
        #pragma unroll
        for (int nt = 0; nt < 4; nt++)
            #pragma unroll
            for (int u = 0; u < 4; u++) acc[mt][nt][u] = 0.f;

    #pragma unroll
    for (int i = 0; i < 4; i++) {
        int c = (p + i) & 3;
        mma_chunk(acc, a_rt + c * 8192, g_W1[c], ns, lane);
        if (i == 0) {
            // acc == part-p pre-activation (chunk p only) for this warp's cols
            float pr[4][2];
            #pragma unroll
            for (int mt = 0; mt < 4; mt++) { pr[mt][0] = 0.f; pr[mt][1] = 0.f; }
            #pragma unroll
            for (int mt = 0; mt < 4; mt++)
                #pragma unroll
                for (int nt = 0; nt < 4; nt++) {
                    int j0 = 32 * ns + 8 * nt + 2 * tg;
                    float bb0 = s_bias[SB_B1 + j0], bb1 = s_bias[SB_B1 + j0 + 1];
                    float wc0 = s_bias[SB_WC + p * 256 + j0];
                    float wc1 = s_bias[SB_WC + p * 256 + j0 + 1];
                    pr[mt][0] = fmaf(fmaxf(acc[mt][nt][0] + bb0, 0.f), wc0, pr[mt][0]);
                    pr[mt][0] = fmaf(fmaxf(acc[mt][nt][1] + bb1, 0.f), wc1, pr[mt][0]);
                    pr[mt][1] = fmaf(fmaxf(acc[mt][nt][2] + bb0, 0.f), wc0, pr[mt][1]);
                    pr[mt][1] = fmaf(fmaxf(acc[mt][nt][3] + bb1, 0.f), wc1, pr[mt][1]);
                }
            #pragma unroll
            for (int mt = 0; mt < 4; mt++)
                #pragma unroll
                for (int hh = 0; hh < 2; hh++) {
                    float v = pr[mt][hh];
                    v += __shfl_xor_sync(0xffffffffu, v, 1);
                    v += __shfl_xor_sync(0xffffffffu, v, 2);
                    if (tg == 0)
                        s_part[(16 * mt + g + 8 * hh) * 8 + ns] = v;
                }
        }
    }
    __syncthreads();               // all X reads done

    // epi L1: y = relu(acc + b1) -> X
    #pragma unroll
    for (int mt = 0; mt < 4; mt++) {
        #pragma unroll
        for (int nt = 0; nt < 4; nt++) {
            int j0 = 32 * ns + 8 * nt + 2 * tg;
            float bb0 = s_bias[SB_B1 + j0], bb1 = s_bias[SB_B1 + j0 + 1];
            uint32_t dst = e_rt + (uint32_t)(j0 >> 4) * 2048u + (uint32_t)mt * 512u
                         + (uint32_t)((nt & 1) * 8);
            sts64(dst,
                  pack2(fmaxf(acc[mt][nt][0] + bb0, 0.f), fmaxf(acc[mt][nt][1] + bb1, 0.f)),
                  pack2(fmaxf(acc[mt][nt][2] + bb0, 0.f), fmaxf(acc[mt][nt][3] + bb1, 0.f)));
        }
    }
    __syncthreads();

    // ================= layer 2 =============================================
    #pragma unroll
    for (int mt = 0; mt < 4; mt++)
        #pragma unroll
        for (int nt = 0; nt < 4; nt++)
            #pragma unroll
            for (int u = 0; u < 4; u++) acc[mt][nt][u] = 0.f;

    #pragma unroll
    for (int i = 0; i < 4; i++) {
        int c = (p + i) & 3;
        mma_chunk(acc, a_rt + c * 8192, g_W2[c], ns, lane);
    }

    // ---- occ head ----
    {
        float pr[4][2];
        #pragma unroll
        for (int mt = 0; mt < 4; mt++) { pr[mt][0] = 0.f; pr[mt][1] = 0.f; }
        #pragma unroll
        for (int mt = 0; mt < 4; mt++)
            #pragma unroll
            for (int nt = 0; nt < 4; nt++) {
                int j0 = 32 * ns + 8 * nt + 2 * tg;
                float bb0 = s_bias[SB_B2 + j0], bb1 = s_bias[SB_B2 + j0 + 1];
                float wo0 = s_bias[SB_WOCC + j0], wo1 = s_bias[SB_WOCC + j0 + 1];
                pr[mt][0] = fmaf(fmaxf(acc[mt][nt][0] + bb0, 0.f), wo0, pr[mt][0]);
                pr[mt][0] = fmaf(fmaxf(acc[mt][nt][1] + bb1, 0.f), wo1, pr[mt][0]);
                pr[mt][1] = fmaf(fmaxf(acc[mt][nt][2] + bb0, 0.f), wo0, pr[mt][1]);
                pr[mt][1] = fmaf(fmaxf(acc[mt][nt][3] + bb1, 0.f), wo1, pr[mt][1]);
            }
        #pragma unroll
        for (int mt = 0; mt < 4; mt++)
            #pragma unroll
            for (int hh = 0; hh < 2; hh++) {
                float v = pr[mt][hh];
                v += __shfl_xor_sync(0xffffffffu, v, 1);
                v += __shfl_xor_sync(0xffffffffu, v, 2);
                if (tg == 0)
                    s_occ[(16 * mt + g + 8 * hh) * 8 + ns] = v;
            }
    }
    __syncthreads();

    // ---- final stores ----
    if (t < 64) {
        int gm = gbase + t;
        if (gm < npts) {
            float s = s_bias[SB_BOCC];
            #pragma unroll
            for (int w = 0; w < 8; w++) s += s_occ[t * 8 + w];
            out[gm] = s;
        }
    }
    {
        int m = t >> 2, pp = t & 3;
        int gm = gbase + m;
        if (gm < npts)
            out[npts + gm * 4 + pp] =
                s_part[m * 8 + 2 * pp] + s_part[m * 8 + 2 * pp + 1] +
                s_bias[SB_BC + pp];
    }
}

// ---------------------------------------------------------------------------
extern "C" void kernel_launch(void* const* d_in, const int* in_sizes, int n_in,
                              void* d_out, int out_size)
{
    const float* coords = (const float*)d_in[0];
    const float* W0   = (const float*)d_in[1];
    const float* b0   = (const float*)d_in[2];
    const float* W1   = (const float*)d_in[3];
    const float* b1   = (const float*)d_in[4];
    const float* W2   = (const float*)d_in[5];
    const float* b2   = (const float*)d_in[6];
    const float* Wocc = (const float*)d_in[7];
    const float* bocc = (const float*)d_in[8];
    const float* Wc   = (const float*)d_in[9];
    const float* bc   = (const float*)d_in[10];
    float* out = (float*)d_out;

    int npts = in_sizes[0] / 3;
    int blocks = (npts + MPB - 1) / MPB;

    prep_kernel<<<576, 256>>>(W0, W1, W2);

    cudaFuncSetAttribute(mlp3d_mma, cudaFuncAttributeMaxDynamicSharedMemorySize,
                         (int)SMEM_TOTAL);
    mlp3d_mma<<<blocks, THREADS, SMEM_TOTAL>>>(coords, b0, b1, b2, Wocc, bocc,
                                               Wc, bc, out, npts);
    (void)n_in; (void)out_size;
}